// round 15
// baseline (speedup 1.0000x reference)
#include <cuda_runtime.h>

#define NN   20000
#define EE   320000
#define CC   128
#define BB   20
#define C3   (3*CC)
#define CAP  96
#define RCUTF 5.0f

typedef unsigned long long u64;

// ---- packed fp32x2 helpers ----
__device__ __forceinline__ u64 pk2(float lo, float hi) {
    u64 r; asm("mov.b64 %0,{%1,%2};" : "=l"(r) : "f"(lo), "f"(hi)); return r;
}
__device__ __forceinline__ u64 pkb(float x) { return pk2(x, x); }
__device__ __forceinline__ void up2(u64 v, float& a, float& b) {
    asm("mov.b64 {%0,%1},%2;" : "=f"(a), "=f"(b) : "l"(v));
}
__device__ __forceinline__ void fma2(u64& d, u64 a, u64 b) {
    asm("fma.rn.f32x2 %0,%1,%2,%0;" : "+l"(d) : "l"(a), "l"(b));
}
__device__ __forceinline__ u64 mul2(u64 a, u64 b) {
    u64 d; asm("mul.rn.f32x2 %0,%1,%2;" : "=l"(d) : "l"(a), "l"(b)); return d;
}
__device__ __forceinline__ u64 add2(u64 a, u64 b) {
    u64 d; asm("add.rn.f32x2 %0,%1,%2;" : "=l"(d) : "l"(a), "l"(b)); return d;
}
__device__ __forceinline__ u64 ld2(const float* p) { return *(const u64*)p; }
__device__ __forceinline__ void st2(float* p, u64 v) { *(u64*)p = v; }

__device__ __forceinline__ float silu_f(float x) { return x / (1.f + __expf(-x)); }

// ---------------- scratch ----------------
__device__ float g_x[(size_t)NN * C3];
__device__ float g_mW[(size_t)NN * C3];
__device__ float g_vn[(size_t)NN * CC];
__device__ float g_sv[(size_t)NN * CC];
__device__ int   g_counts[NN];
__device__ int   g_perm[(size_t)NN * CAP];

// ---------------- zero counts ----------------
__global__ void k_zero() {
    int i = blockIdx.x * blockDim.x + threadIdx.x;
    if (i < NN) g_counts[i] = 0;
}

// ---------------- tiny dummy (keeps profiled slot aligned) ----------------
__global__ void k_dummy() {
    int i = blockIdx.x * blockDim.x + threadIdx.x;
    if (i < NN) g_vn[i] = 0.f;
}

// ---------------- bucket CSR ----------------
__global__ void k_bucket(const int* __restrict__ eidx) {
    int e = blockIdx.x * blockDim.x + threadIdx.x;
    if (e < EE) {
        int i = eidx[e];
        int slot = atomicAdd(&g_counts[i], 1);
        if (slot < CAP) g_perm[(size_t)i * CAP + slot] = e;
    }
}

// ---------------- node context: 48 rows/block; smem-staged weight tiles ----------------
// 8 warps x 6 rows; thread tx owns 4 consecutive cols (4tx..4tx+3).
// Weights bulk-loaded into 32-k smem tiles (coalesced LDG.128), compute is pure LDS+FFMA2.
#define KT 32
__global__ __launch_bounds__(256) void k_context(
    const float* __restrict__ q,
    const float* __restrict__ W1, const float* __restrict__ b1,
    const float* __restrict__ W2, const float* __restrict__ b2)
{
    __shared__ float qs[48][CC];     // 24KB
    __shared__ float hs[48][CC];     // 24KB
    __shared__ float wt[KT][CC];     // 16KB
    int tid = threadIdx.x, tx = tid & 31, ty = tid >> 5;
    int c0 = 4 * tx;
    int rowbase = blockIdx.x * 48;

    for (int idx = tid; idx < 48 * CC; idx += 256) {
        int r = idx >> 7, c = idx & 127;
        int gr = rowbase + r;
        qs[r][c] = (gr < NN) ? q[(size_t)gr * CC + c] : 0.f;
    }
    __syncthreads();

    // stage 1: h = silu(q@W1 + b1)
    {
        u64 acc[6][2];
        #pragma unroll
        for (int r = 0; r < 6; r++) { acc[r][0] = 0; acc[r][1] = 0; }
        for (int kt = 0; kt < CC; kt += KT) {
            // load weight tile (4 x LDG.128 per thread, independent)
            #pragma unroll
            for (int l = 0; l < 4; l++) {
                int idx = tid + l * 256;                 // [0,1024) float4 index
                int r = idx >> 5, c4 = (idx & 31) * 4;   // row in tile, col
                *(float4*)(&wt[r][c4]) = *(const float4*)(W1 + (kt + r) * CC + c4);
            }
            __syncthreads();
            for (int k = 0; k < KT; k += 2) {
                ulonglong2 wa = *(const ulonglong2*)(&wt[k][c0]);
                ulonglong2 wb = *(const ulonglong2*)(&wt[k + 1][c0]);
                #pragma unroll
                for (int r = 0; r < 6; r++) {
                    float2 a = *(const float2*)(&qs[ty * 6 + r][kt + k]);
                    u64 p0 = pkb(a.x), p1 = pkb(a.y);
                    fma2(acc[r][0], p0, wa.x);
                    fma2(acc[r][1], p0, wa.y);
                    fma2(acc[r][0], p1, wb.x);
                    fma2(acc[r][1], p1, wb.y);
                }
            }
            __syncthreads();
        }
        float b1v0 = b1[c0], b1v1 = b1[c0 + 1], b1v2 = b1[c0 + 2], b1v3 = b1[c0 + 3];
        #pragma unroll
        for (int r = 0; r < 6; r++) {
            float a0, a1, a2, a3;
            up2(acc[r][0], a0, a1);
            up2(acc[r][1], a2, a3);
            hs[ty * 6 + r][c0]     = silu_f(a0 + b1v0);
            hs[ty * 6 + r][c0 + 1] = silu_f(a1 + b1v1);
            hs[ty * 6 + r][c0 + 2] = silu_f(a2 + b1v2);
            hs[ty * 6 + r][c0 + 3] = silu_f(a3 + b1v3);
        }
    }
    __syncthreads();

    // stage 2: x = h@W2 + b2 (3 col-chunks)
    for (int ch = 0; ch < 3; ch++) {
        u64 acc[6][2];
        #pragma unroll
        for (int r = 0; r < 6; r++) { acc[r][0] = 0; acc[r][1] = 0; }
        for (int kt = 0; kt < CC; kt += KT) {
            #pragma unroll
            for (int l = 0; l < 4; l++) {
                int idx = tid + l * 256;
                int r = idx >> 5, c4 = (idx & 31) * 4;
                *(float4*)(&wt[r][c4]) = *(const float4*)(W2 + (size_t)(kt + r) * C3 + ch * CC + c4);
            }
            __syncthreads();
            for (int k = 0; k < KT; k += 2) {
                ulonglong2 wa = *(const ulonglong2*)(&wt[k][c0]);
                ulonglong2 wb = *(const ulonglong2*)(&wt[k + 1][c0]);
                #pragma unroll
                for (int r = 0; r < 6; r++) {
                    float2 a = *(const float2*)(&hs[ty * 6 + r][kt + k]);
                    u64 p0 = pkb(a.x), p1 = pkb(a.y);
                    fma2(acc[r][0], p0, wa.x);
                    fma2(acc[r][1], p0, wa.y);
                    fma2(acc[r][0], p1, wb.x);
                    fma2(acc[r][1], p1, wb.y);
                }
            }
            __syncthreads();
        }
        u64 bb0 = ld2(b2 + ch * CC + c0);
        u64 bb1 = ld2(b2 + ch * CC + c0 + 2);
        #pragma unroll
        for (int r = 0; r < 6; r++) {
            int gr = rowbase + ty * 6 + r;
            if (gr < NN) {
                ulonglong2 o;
                o.x = add2(acc[r][0], bb0);
                o.y = add2(acc[r][1], bb1);
                *(ulonglong2*)(g_x + (size_t)gr * C3 + ch * CC + c0) = o;
            }
        }
    }
}

// ---------------- fused filter + aggregation (R8 config, best measured) ----------------
__global__ __launch_bounds__(192, 4) void k_aggregate(
    const float* __restrict__ q, const float* __restrict__ mu,
    const int* __restrict__ eidx, const float* __restrict__ ew,
    const float* __restrict__ ev, const float* __restrict__ ea,
    const float* __restrict__ Wf, const float* __restrict__ bf,
    float* __restrict__ outq, float* __restrict__ outmu)
{
    __shared__ int   s_j[CAP];
    __shared__ float s_fc[CAP];
    __shared__ float s_ev[CAP][4];
    __shared__ __align__(16) u64 s_eap[CAP][BB];
    __shared__ float s_m[3][CC];
    __shared__ int   s_etmp[CAP];

    int i = blockIdx.x;
    int tid = threadIdx.x;
    int grp = tid >> 6, t = tid & 63, t2 = 2 * t;
    const int* __restrict__ idx_j = eidx + EE;

    int cnt = g_counts[i]; if (cnt > CAP) cnt = CAP;

    if (tid < cnt) {
        int e = g_perm[(size_t)i * CAP + tid];
        s_etmp[tid] = e;
        s_j[tid] = idx_j[e];
        float w = ew[e];
        s_fc[tid] = (w < RCUTF) ? 0.5f * (cospif(w * (1.0f / RCUTF)) + 1.f) : 0.f;
        s_ev[tid][0] = ev[e * 3 + 0];
        s_ev[tid][1] = ev[e * 3 + 1];
        s_ev[tid][2] = ev[e * 3 + 2];
    }
    __syncthreads();
    for (int idx = tid; idx < cnt * BB; idx += 192) {
        float v = ea[(size_t)s_etmp[idx / BB] * BB + (idx % BB)];
        s_eap[idx / BB][idx % BB] = pkb(v);
    }
    __syncthreads();

    u64 wfp[BB];
    #pragma unroll
    for (int b = 0; b < BB; b++) wfp[b] = ld2(Wf + b * C3 + grp * CC + t2);
    u64 bfp = ld2(bf + grp * CC + t2);

    u64 acc0 = 0, m0 = 0, m1 = 0, m2 = 0;
    if (grp == 0) acc0 = ld2(q + (size_t)i * CC + t2);
    if (grp == 1) {
        const float* mi = mu + (size_t)i * C3;
        m0 = ld2(mi + t2); m1 = ld2(mi + CC + t2); m2 = ld2(mi + 2 * CC + t2);
    }

    u64 xn = 0;
    if (cnt > 0) xn = ld2(g_x + (size_t)s_j[0] * C3 + grp * CC + t2);

    for (int p = 0; p < cnt; p++) {
        u64 x = xn;
        int j = s_j[p];
        if (p + 1 < cnt) xn = ld2(g_x + (size_t)s_j[p + 1] * C3 + grp * CC + t2);

        const ulonglong2* __restrict__ av2 = (const ulonglong2*)s_eap[p];
        u64 a0 = bfp, a1 = 0, a2 = 0, a3 = 0;
        #pragma unroll
        for (int b = 0; b < 10; b += 2) {
            ulonglong2 v01 = av2[b];
            ulonglong2 v23 = av2[b + 1];
            fma2(a0, v01.x, wfp[2 * b]);
            fma2(a1, v01.y, wfp[2 * b + 1]);
            fma2(a2, v23.x, wfp[2 * b + 2]);
            fma2(a3, v23.y, wfp[2 * b + 3]);
        }
        u64 a = mul2(add2(add2(a0, a1), add2(a2, a3)), pkb(s_fc[p]));

        if (grp == 0) {
            fma2(acc0, x, a);
        } else if (grp == 1) {
            u64 dR = mul2(x, a);
            fma2(m0, dR, pkb(s_ev[p][0]));
            fma2(m1, dR, pkb(s_ev[p][1]));
            fma2(m2, dR, pkb(s_ev[p][2]));
        } else {
            u64 dm = mul2(x, a);
            const float* __restrict__ mj = mu + (size_t)j * C3;
            fma2(m0, dm, ld2(mj + t2));
            fma2(m1, dm, ld2(mj + CC + t2));
            fma2(m2, dm, ld2(mj + 2 * CC + t2));
        }
    }

    if (grp == 2) {
        st2(&s_m[0][t2], m0);
        st2(&s_m[1][t2], m1);
        st2(&s_m[2][t2], m2);
    }
    __syncthreads();
    if (grp == 0) st2(outq + (size_t)i * CC + t2, acc0);
    if (grp == 1) {
        float* mo = outmu + (size_t)i * C3;
        st2(mo + t2,          add2(m0, ld2(&s_m[0][t2])));
        st2(mo + CC + t2,     add2(m1, ld2(&s_m[1][t2])));
        st2(mo + 2 * CC + t2, add2(m2, ld2(&s_m[2][t2])));
    }
}

// ---------------- mixing stage A: wide columns (LDG.128 weights) ----------------
// thread tx owns V cols 4tx..4tx+3 and W cols 4tx..4tx+3; warp owns 6 mu-rows = 2 nodes
__global__ __launch_bounds__(256) void k_mixA(
    const float* __restrict__ outmu, const float* __restrict__ Wmix)
{
    __shared__ float mus[48][CC];
    int tid = threadIdx.x, tx = tid & 31, wp = tid >> 5;
    int c0 = 4 * tx;
    int base_row = blockIdx.x * 48;

    for (int idx = tid; idx < 48 * CC; idx += 256)
        ((float*)mus)[idx] = outmu[(size_t)base_row * CC + idx];
    __syncthreads();

    u64 accV[6][2], accW[6][2];
    #pragma unroll
    for (int r = 0; r < 6; r++) { accV[r][0] = accV[r][1] = accW[r][0] = accW[r][1] = 0; }

    for (int k = 0; k < CC; k += 2) {
        ulonglong2 wva = *(const ulonglong2*)(Wmix + k * 2 * CC + c0);
        ulonglong2 wwa = *(const ulonglong2*)(Wmix + k * 2 * CC + CC + c0);
        ulonglong2 wvb = *(const ulonglong2*)(Wmix + (k + 1) * 2 * CC + c0);
        ulonglong2 wwb = *(const ulonglong2*)(Wmix + (k + 1) * 2 * CC + CC + c0);
        #pragma unroll
        for (int r = 0; r < 6; r++) {
            float2 a = *(const float2*)(&mus[wp * 6 + r][k]);
            u64 p0 = pkb(a.x), p1 = pkb(a.y);
            fma2(accV[r][0], p0, wva.x);
            fma2(accV[r][1], p0, wva.y);
            fma2(accW[r][0], p0, wwa.x);
            fma2(accW[r][1], p0, wwa.y);
            fma2(accV[r][0], p1, wvb.x);
            fma2(accV[r][1], p1, wvb.y);
            fma2(accW[r][0], p1, wwb.x);
            fma2(accW[r][1], p1, wwb.y);
        }
    }

    #pragma unroll
    for (int r = 0; r < 6; r++) {
        int grow = base_row + wp * 6 + r;
        ulonglong2 o; o.x = accW[r][0]; o.y = accW[r][1];
        *(ulonglong2*)(g_mW + (size_t)grow * CC + c0) = o;
    }
    #pragma unroll
    for (int ln = 0; ln < 2; ln++) {
        int node = (base_row / 3) + wp * 2 + ln;
        #pragma unroll
        for (int c = 0; c < 2; c++) {
            float v0a, v0b, v1a, v1b, v2a, v2b, w0a, w0b, w1a, w1b, w2a, w2b;
            up2(accV[ln * 3 + 0][c], v0a, v0b);
            up2(accV[ln * 3 + 1][c], v1a, v1b);
            up2(accV[ln * 3 + 2][c], v2a, v2b);
            up2(accW[ln * 3 + 0][c], w0a, w0b);
            up2(accW[ln * 3 + 1][c], w1a, w1b);
            up2(accW[ln * 3 + 2][c], w2a, w2b);
            float na = sqrtf(v0a * v0a + v1a * v1a + v2a * v2a + 1e-8f);
            float nb = sqrtf(v0b * v0b + v1b * v1b + v2b * v2b + 1e-8f);
            float sa = v0a * w0a + v1a * w1a + v2a * w2a;
            float sb = v0b * w0b + v1b * w1b + v2b * w2b;
            int col = c0 + 2 * c;
            st2(g_vn + (size_t)node * CC + col, pk2(na, nb));
            st2(g_sv + (size_t)node * CC + col, pk2(sa, sb));
        }
    }
}

// ---------------- mixing stage B: 16 nodes/block; LDG.128 weights (R11, best measured) ----------------
__global__ __launch_bounds__(256) void k_mixB(
    float* __restrict__ outq, float* __restrict__ outmu,
    const float* __restrict__ Wm1, const float* __restrict__ bm1,
    const float* __restrict__ Wm2, const float* __restrict__ bm2)
{
    __shared__ float qs[16][CC];
    __shared__ float vns[16][CC];
    __shared__ float hs[16][CC];
    int tid = threadIdx.x, tx = tid & 31, wp = tid >> 5;
    int c0 = 4 * tx;
    int nb = blockIdx.x * 16;

    for (int idx = tid; idx < 16 * CC; idx += 256) {
        ((float*)qs)[idx]  = outq[(size_t)nb * CC + idx];
        ((float*)vns)[idx] = g_vn[(size_t)nb * CC + idx];
    }
    __syncthreads();

    {
        u64 acc[2][2];
        #pragma unroll
        for (int r = 0; r < 2; r++) { acc[r][0] = 0; acc[r][1] = 0; }
        for (int k = 0; k < CC; k += 2) {
            ulonglong2 wa = *(const ulonglong2*)(Wm1 + k * CC + c0);
            ulonglong2 wb = *(const ulonglong2*)(Wm1 + (k + 1) * CC + c0);
            #pragma unroll
            for (int r = 0; r < 2; r++) {
                float2 a = *(const float2*)(&qs[wp * 2 + r][k]);
                u64 p0 = pkb(a.x), p1 = pkb(a.y);
                fma2(acc[r][0], p0, wa.x);
                fma2(acc[r][1], p0, wa.y);
                fma2(acc[r][0], p1, wb.x);
                fma2(acc[r][1], p1, wb.y);
            }
        }
        for (int k = 0; k < CC; k += 2) {
            ulonglong2 wa = *(const ulonglong2*)(Wm1 + (CC + k) * CC + c0);
            ulonglong2 wb = *(const ulonglong2*)(Wm1 + (CC + k + 1) * CC + c0);
            #pragma unroll
            for (int r = 0; r < 2; r++) {
                float2 a = *(const float2*)(&vns[wp * 2 + r][k]);
                u64 p0 = pkb(a.x), p1 = pkb(a.y);
                fma2(acc[r][0], p0, wa.x);
                fma2(acc[r][1], p0, wa.y);
                fma2(acc[r][0], p1, wb.x);
                fma2(acc[r][1], p1, wb.y);
            }
        }
        float bv0 = bm1[c0], bv1 = bm1[c0 + 1], bv2 = bm1[c0 + 2], bv3 = bm1[c0 + 3];
        #pragma unroll
        for (int r = 0; r < 2; r++) {
            float a0, a1, a2, a3;
            up2(acc[r][0], a0, a1);
            up2(acc[r][1], a2, a3);
            hs[wp * 2 + r][c0]     = silu_f(a0 + bv0);
            hs[wp * 2 + r][c0 + 1] = silu_f(a1 + bv1);
            hs[wp * 2 + r][c0 + 2] = silu_f(a2 + bv2);
            hs[wp * 2 + r][c0 + 3] = silu_f(a3 + bv3);
        }
    }
    __syncwarp();

    u64 y0p[2][2];
    for (int ch = 0; ch < 3; ch++) {
        u64 acc[2][2];
        #pragma unroll
        for (int r = 0; r < 2; r++) { acc[r][0] = 0; acc[r][1] = 0; }
        for (int k = 0; k < CC; k += 2) {
            ulonglong2 wa = *(const ulonglong2*)(Wm2 + k * C3 + ch * CC + c0);
            ulonglong2 wb = *(const ulonglong2*)(Wm2 + (k + 1) * C3 + ch * CC + c0);
            #pragma unroll
            for (int r = 0; r < 2; r++) {
                float2 a = *(const float2*)(&hs[wp * 2 + r][k]);
                u64 p0 = pkb(a.x), p1 = pkb(a.y);
                fma2(acc[r][0], p0, wa.x);
                fma2(acc[r][1], p0, wa.y);
                fma2(acc[r][0], p1, wb.x);
                fma2(acc[r][1], p1, wb.y);
            }
        }
        if (ch == 0) {
            u64 bb0 = ld2(bm2 + c0), bb1 = ld2(bm2 + c0 + 2);
            #pragma unroll
            for (int r = 0; r < 2; r++) {
                y0p[r][0] = add2(acc[r][0], bb0);
                y0p[r][1] = add2(acc[r][1], bb1);
            }
        } else if (ch == 1) {
            u64 bb0 = ld2(bm2 + CC + c0), bb1 = ld2(bm2 + CC + c0 + 2);
            #pragma unroll
            for (int r = 0; r < 2; r++) {
                int node = nb + wp * 2 + r;
                u64 y1a = add2(acc[r][0], bb0);
                u64 y1b = add2(acc[r][1], bb1);
                #pragma unroll
                for (int v = 0; v < 3; v++) {
                    size_t off = ((size_t)node * 3 + v) * CC + c0;
                    u64 d0 = ld2(outmu + off);
                    u64 d1 = ld2(outmu + off + 2);
                    fma2(d0, y1a, ld2(g_mW + off));
                    fma2(d1, y1b, ld2(g_mW + off + 2));
                    st2(outmu + off, d0);
                    st2(outmu + off + 2, d1);
                }
            }
        } else {
            u64 bb0 = ld2(bm2 + 2 * CC + c0), bb1 = ld2(bm2 + 2 * CC + c0 + 2);
            #pragma unroll
            for (int r = 0; r < 2; r++) {
                int node = nb + wp * 2 + r;
                u64 y2a = add2(acc[r][0], bb0);
                u64 y2b = add2(acc[r][1], bb1);
                u64 d0 = add2(ld2(&qs[wp * 2 + r][c0]), y0p[r][0]);
                u64 d1 = add2(ld2(&qs[wp * 2 + r][c0 + 2]), y0p[r][1]);
                fma2(d0, y2a, ld2(g_sv + (size_t)node * CC + c0));
                fma2(d1, y2b, ld2(g_sv + (size_t)node * CC + c0 + 2));
                st2(outq + (size_t)node * CC + c0, d0);
                st2(outq + (size_t)node * CC + c0 + 2, d1);
            }
        }
    }
}

// ---------------- launch ----------------
extern "C" void kernel_launch(void* const* d_in, const int* in_sizes, int n_in,
                              void* d_out, int out_size)
{
    const float* q    = (const float*)d_in[0];
    const float* mu   = (const float*)d_in[1];
    const int*   eidx = (const int*)  d_in[2];
    const float* ew   = (const float*)d_in[3];
    const float* ev   = (const float*)d_in[4];
    const float* ea   = (const float*)d_in[5];
    const float* Wf   = (const float*)d_in[6];
    const float* bf   = (const float*)d_in[7];
    const float* W1   = (const float*)d_in[8];
    const float* b1   = (const float*)d_in[9];
    const float* W2   = (const float*)d_in[10];
    const float* b2   = (const float*)d_in[11];
    const float* Wmix = (const float*)d_in[12];
    const float* Wm1  = (const float*)d_in[13];
    const float* bm1  = (const float*)d_in[14];
    const float* Wm2  = (const float*)d_in[15];
    const float* bm2  = (const float*)d_in[16];

    float* outq  = (float*)d_out;
    float* outmu = outq + (size_t)NN * CC;

    // profiled slot = my launch index 3 => new k_context
    k_zero<<<(NN + 255) / 256, 256>>>();                                // 0
    k_bucket<<<(EE + 255) / 256, 256>>>(eidx);                          // 1
    k_dummy<<<(NN + 255) / 256, 256>>>();                               // 2 (tiny)
    k_context<<<(NN + 47) / 48, 256>>>(q, W1, b1, W2, b2);              // 3 <- profiled
    k_aggregate<<<NN, 192>>>(q, mu, eidx, ew, ev, ea, Wf, bf, outq, outmu); // 4
    k_mixA<<<NN / 16, 256>>>(outmu, Wmix);                              // 5
    k_mixB<<<NN / 16, 256>>>(outq, outmu, Wm1, bm1, Wm2, bm2);          // 6
}

// round 16
// speedup vs baseline: 1.4222x; 1.4222x over previous
#include <cuda_runtime.h>

#define NN   20000
#define EE   320000
#define CC   128
#define BB   20
#define C3   (3*CC)
#define CAP  96
#define RCUTF 5.0f

typedef unsigned long long u64;

// ---- packed fp32x2 helpers ----
__device__ __forceinline__ u64 pk2(float lo, float hi) {
    u64 r; asm("mov.b64 %0,{%1,%2};" : "=l"(r) : "f"(lo), "f"(hi)); return r;
}
__device__ __forceinline__ u64 pkb(float x) { return pk2(x, x); }
__device__ __forceinline__ void up2(u64 v, float& a, float& b) {
    asm("mov.b64 {%0,%1},%2;" : "=f"(a), "=f"(b) : "l"(v));
}
__device__ __forceinline__ void fma2(u64& d, u64 a, u64 b) {
    asm("fma.rn.f32x2 %0,%1,%2,%0;" : "+l"(d) : "l"(a), "l"(b));
}
__device__ __forceinline__ u64 mul2(u64 a, u64 b) {
    u64 d; asm("mul.rn.f32x2 %0,%1,%2;" : "=l"(d) : "l"(a), "l"(b)); return d;
}
__device__ __forceinline__ u64 add2(u64 a, u64 b) {
    u64 d; asm("add.rn.f32x2 %0,%1,%2;" : "=l"(d) : "l"(a), "l"(b)); return d;
}
__device__ __forceinline__ u64 ld2(const float* p) { return *(const u64*)p; }
__device__ __forceinline__ void st2(float* p, u64 v) { *(u64*)p = v; }

__device__ __forceinline__ float silu_f(float x) { return x / (1.f + __expf(-x)); }

// ---------------- scratch ----------------
__device__ float g_x[(size_t)NN * C3];
__device__ float g_mW[(size_t)NN * C3];
__device__ float g_vn[(size_t)NN * CC];
__device__ float g_sv[(size_t)NN * CC];
__device__ int   g_counts[NN];
__device__ int   g_perm[(size_t)NN * CAP];

// ---------------- zero counts ----------------
__global__ void k_zero() {
    int i = blockIdx.x * blockDim.x + threadIdx.x;
    if (i < NN) g_counts[i] = 0;
}

// ---------------- tiny dummy (keeps profiled slot aligned) ----------------
__global__ void k_dummy() {
    int i = blockIdx.x * blockDim.x + threadIdx.x;
    if (i < NN) g_vn[i] = 0.f;
}

// ---------------- bucket CSR ----------------
__global__ void k_bucket(const int* __restrict__ eidx) {
    int e = blockIdx.x * blockDim.x + threadIdx.x;
    if (e < EE) {
        int i = eidx[e];
        int slot = atomicAdd(&g_counts[i], 1);
        if (slot < CAP) g_perm[(size_t)i * CAP + slot] = e;
    }
}

// ---------------- node context: 48 rows/block; smem-staged weight tiles (R14, measured 116us) ----------------
#define KT 32
__global__ __launch_bounds__(256) void k_context(
    const float* __restrict__ q,
    const float* __restrict__ W1, const float* __restrict__ b1,
    const float* __restrict__ W2, const float* __restrict__ b2)
{
    __shared__ float qs[48][CC];     // 24KB
    __shared__ float hs[48][CC];     // 24KB
    __shared__ float wt[KT][CC];     // 16KB
    int tid = threadIdx.x, tx = tid & 31, ty = tid >> 5;
    int c0 = 4 * tx;
    int rowbase = blockIdx.x * 48;

    for (int idx = tid; idx < 48 * CC; idx += 256) {
        int r = idx >> 7, c = idx & 127;
        int gr = rowbase + r;
        qs[r][c] = (gr < NN) ? q[(size_t)gr * CC + c] : 0.f;
    }
    __syncthreads();

    // stage 1: h = silu(q@W1 + b1)
    {
        u64 acc[6][2];
        #pragma unroll
        for (int r = 0; r < 6; r++) { acc[r][0] = 0; acc[r][1] = 0; }
        for (int kt = 0; kt < CC; kt += KT) {
            #pragma unroll
            for (int l = 0; l < 4; l++) {
                int idx = tid + l * 256;
                int r = idx >> 5, c4 = (idx & 31) * 4;
                *(float4*)(&wt[r][c4]) = *(const float4*)(W1 + (kt + r) * CC + c4);
            }
            __syncthreads();
            for (int k = 0; k < KT; k += 2) {
                ulonglong2 wa = *(const ulonglong2*)(&wt[k][c0]);
                ulonglong2 wb = *(const ulonglong2*)(&wt[k + 1][c0]);
                #pragma unroll
                for (int r = 0; r < 6; r++) {
                    float2 a = *(const float2*)(&qs[ty * 6 + r][kt + k]);
                    u64 p0 = pkb(a.x), p1 = pkb(a.y);
                    fma2(acc[r][0], p0, wa.x);
                    fma2(acc[r][1], p0, wa.y);
                    fma2(acc[r][0], p1, wb.x);
                    fma2(acc[r][1], p1, wb.y);
                }
            }
            __syncthreads();
        }
        float b1v0 = b1[c0], b1v1 = b1[c0 + 1], b1v2 = b1[c0 + 2], b1v3 = b1[c0 + 3];
        #pragma unroll
        for (int r = 0; r < 6; r++) {
            float a0, a1, a2, a3;
            up2(acc[r][0], a0, a1);
            up2(acc[r][1], a2, a3);
            hs[ty * 6 + r][c0]     = silu_f(a0 + b1v0);
            hs[ty * 6 + r][c0 + 1] = silu_f(a1 + b1v1);
            hs[ty * 6 + r][c0 + 2] = silu_f(a2 + b1v2);
            hs[ty * 6 + r][c0 + 3] = silu_f(a3 + b1v3);
        }
    }
    __syncthreads();

    // stage 2: x = h@W2 + b2 (3 col-chunks)
    for (int ch = 0; ch < 3; ch++) {
        u64 acc[6][2];
        #pragma unroll
        for (int r = 0; r < 6; r++) { acc[r][0] = 0; acc[r][1] = 0; }
        for (int kt = 0; kt < CC; kt += KT) {
            #pragma unroll
            for (int l = 0; l < 4; l++) {
                int idx = tid + l * 256;
                int r = idx >> 5, c4 = (idx & 31) * 4;
                *(float4*)(&wt[r][c4]) = *(const float4*)(W2 + (size_t)(kt + r) * C3 + ch * CC + c4);
            }
            __syncthreads();
            for (int k = 0; k < KT; k += 2) {
                ulonglong2 wa = *(const ulonglong2*)(&wt[k][c0]);
                ulonglong2 wb = *(const ulonglong2*)(&wt[k + 1][c0]);
                #pragma unroll
                for (int r = 0; r < 6; r++) {
                    float2 a = *(const float2*)(&hs[ty * 6 + r][kt + k]);
                    u64 p0 = pkb(a.x), p1 = pkb(a.y);
                    fma2(acc[r][0], p0, wa.x);
                    fma2(acc[r][1], p0, wa.y);
                    fma2(acc[r][0], p1, wb.x);
                    fma2(acc[r][1], p1, wb.y);
                }
            }
            __syncthreads();
        }
        u64 bb0 = ld2(b2 + ch * CC + c0);
        u64 bb1 = ld2(b2 + ch * CC + c0 + 2);
        #pragma unroll
        for (int r = 0; r < 6; r++) {
            int gr = rowbase + ty * 6 + r;
            if (gr < NN) {
                ulonglong2 o;
                o.x = add2(acc[r][0], bb0);
                o.y = add2(acc[r][1], bb1);
                *(ulonglong2*)(g_x + (size_t)gr * C3 + ch * CC + c0) = o;
            }
        }
    }
}

// ---------------- fused filter + aggregation (R8 config, best measured) ----------------
__global__ __launch_bounds__(192, 4) void k_aggregate(
    const float* __restrict__ q, const float* __restrict__ mu,
    const int* __restrict__ eidx, const float* __restrict__ ew,
    const float* __restrict__ ev, const float* __restrict__ ea,
    const float* __restrict__ Wf, const float* __restrict__ bf,
    float* __restrict__ outq, float* __restrict__ outmu)
{
    __shared__ int   s_j[CAP];
    __shared__ float s_fc[CAP];
    __shared__ float s_ev[CAP][4];
    __shared__ __align__(16) u64 s_eap[CAP][BB];
    __shared__ float s_m[3][CC];
    __shared__ int   s_etmp[CAP];

    int i = blockIdx.x;
    int tid = threadIdx.x;
    int grp = tid >> 6, t = tid & 63, t2 = 2 * t;
    const int* __restrict__ idx_j = eidx + EE;

    int cnt = g_counts[i]; if (cnt > CAP) cnt = CAP;

    if (tid < cnt) {
        int e = g_perm[(size_t)i * CAP + tid];
        s_etmp[tid] = e;
        s_j[tid] = idx_j[e];
        float w = ew[e];
        s_fc[tid] = (w < RCUTF) ? 0.5f * (cospif(w * (1.0f / RCUTF)) + 1.f) : 0.f;
        s_ev[tid][0] = ev[e * 3 + 0];
        s_ev[tid][1] = ev[e * 3 + 1];
        s_ev[tid][2] = ev[e * 3 + 2];
    }
    __syncthreads();
    for (int idx = tid; idx < cnt * BB; idx += 192) {
        float v = ea[(size_t)s_etmp[idx / BB] * BB + (idx % BB)];
        s_eap[idx / BB][idx % BB] = pkb(v);
    }
    __syncthreads();

    u64 wfp[BB];
    #pragma unroll
    for (int b = 0; b < BB; b++) wfp[b] = ld2(Wf + b * C3 + grp * CC + t2);
    u64 bfp = ld2(bf + grp * CC + t2);

    u64 acc0 = 0, m0 = 0, m1 = 0, m2 = 0;
    if (grp == 0) acc0 = ld2(q + (size_t)i * CC + t2);
    if (grp == 1) {
        const float* mi = mu + (size_t)i * C3;
        m0 = ld2(mi + t2); m1 = ld2(mi + CC + t2); m2 = ld2(mi + 2 * CC + t2);
    }

    u64 xn = 0;
    if (cnt > 0) xn = ld2(g_x + (size_t)s_j[0] * C3 + grp * CC + t2);

    for (int p = 0; p < cnt; p++) {
        u64 x = xn;
        int j = s_j[p];
        if (p + 1 < cnt) xn = ld2(g_x + (size_t)s_j[p + 1] * C3 + grp * CC + t2);

        const ulonglong2* __restrict__ av2 = (const ulonglong2*)s_eap[p];
        u64 a0 = bfp, a1 = 0, a2 = 0, a3 = 0;
        #pragma unroll
        for (int b = 0; b < 10; b += 2) {
            ulonglong2 v01 = av2[b];
            ulonglong2 v23 = av2[b + 1];
            fma2(a0, v01.x, wfp[2 * b]);
            fma2(a1, v01.y, wfp[2 * b + 1]);
            fma2(a2, v23.x, wfp[2 * b + 2]);
            fma2(a3, v23.y, wfp[2 * b + 3]);
        }
        u64 a = mul2(add2(add2(a0, a1), add2(a2, a3)), pkb(s_fc[p]));

        if (grp == 0) {
            fma2(acc0, x, a);
        } else if (grp == 1) {
            u64 dR = mul2(x, a);
            fma2(m0, dR, pkb(s_ev[p][0]));
            fma2(m1, dR, pkb(s_ev[p][1]));
            fma2(m2, dR, pkb(s_ev[p][2]));
        } else {
            u64 dm = mul2(x, a);
            const float* __restrict__ mj = mu + (size_t)j * C3;
            fma2(m0, dm, ld2(mj + t2));
            fma2(m1, dm, ld2(mj + CC + t2));
            fma2(m2, dm, ld2(mj + 2 * CC + t2));
        }
    }

    if (grp == 2) {
        st2(&s_m[0][t2], m0);
        st2(&s_m[1][t2], m1);
        st2(&s_m[2][t2], m2);
    }
    __syncthreads();
    if (grp == 0) st2(outq + (size_t)i * CC + t2, acc0);
    if (grp == 1) {
        float* mo = outmu + (size_t)i * C3;
        st2(mo + t2,          add2(m0, ld2(&s_m[0][t2])));
        st2(mo + CC + t2,     add2(m1, ld2(&s_m[1][t2])));
        st2(mo + 2 * CC + t2, add2(m2, ld2(&s_m[2][t2])));
    }
}

// ---------------- mixing stage A (reverted to R12 measured-best form, 119us) ----------------
__global__ __launch_bounds__(256) void k_mixA(
    const float* __restrict__ outmu, const float* __restrict__ Wmix)
{
    __shared__ float mus[48][CC];
    int tid = threadIdx.x, tx = tid & 31, wp = tid >> 5;
    int t2 = 2 * tx;
    int base_row = blockIdx.x * 48;

    for (int idx = tid; idx < 48 * CC; idx += 256)
        ((float*)mus)[idx] = outmu[(size_t)base_row * CC + idx];
    __syncthreads();

    u64 accV[6][2], accW[6][2];
    #pragma unroll
    for (int r = 0; r < 6; r++) { accV[r][0] = accV[r][1] = accW[r][0] = accW[r][1] = 0; }

    for (int k = 0; k < CC; k++) {
        u64 wv0 = ld2(Wmix + k * 2 * CC + t2);
        u64 wv1 = ld2(Wmix + k * 2 * CC + 64 + t2);
        u64 ww0 = ld2(Wmix + k * 2 * CC + CC + t2);
        u64 ww1 = ld2(Wmix + k * 2 * CC + CC + 64 + t2);
        #pragma unroll
        for (int r = 0; r < 6; r++) {
            u64 aa = pkb(mus[wp * 6 + r][k]);
            fma2(accV[r][0], aa, wv0);
            fma2(accV[r][1], aa, wv1);
            fma2(accW[r][0], aa, ww0);
            fma2(accW[r][1], aa, ww1);
        }
    }

    #pragma unroll
    for (int r = 0; r < 6; r++) {
        int grow = base_row + wp * 6 + r;
        #pragma unroll
        for (int c = 0; c < 2; c++)
            st2(g_mW + (size_t)grow * CC + 64 * c + t2, accW[r][c]);
    }
    #pragma unroll
    for (int ln = 0; ln < 2; ln++) {
        int node = (base_row / 3) + wp * 2 + ln;
        #pragma unroll
        for (int c = 0; c < 2; c++) {
            float v0a, v0b, v1a, v1b, v2a, v2b, w0a, w0b, w1a, w1b, w2a, w2b;
            up2(accV[ln * 3 + 0][c], v0a, v0b);
            up2(accV[ln * 3 + 1][c], v1a, v1b);
            up2(accV[ln * 3 + 2][c], v2a, v2b);
            up2(accW[ln * 3 + 0][c], w0a, w0b);
            up2(accW[ln * 3 + 1][c], w1a, w1b);
            up2(accW[ln * 3 + 2][c], w2a, w2b);
            float na = sqrtf(v0a * v0a + v1a * v1a + v2a * v2a + 1e-8f);
            float nb = sqrtf(v0b * v0b + v1b * v1b + v2b * v2b + 1e-8f);
            float sa = v0a * w0a + v1a * w1a + v2a * w2a;
            float sb = v0b * w0b + v1b * w1b + v2b * w2b;
            int col = 64 * c + t2;
            st2(g_vn + (size_t)node * CC + col, pk2(na, nb));
            st2(g_sv + (size_t)node * CC + col, pk2(sa, sb));
        }
    }
}

// ---------------- mixing stage B: 16 nodes/block; LDG.128 weights (R11, best measured) ----------------
__global__ __launch_bounds__(256) void k_mixB(
    float* __restrict__ outq, float* __restrict__ outmu,
    const float* __restrict__ Wm1, const float* __restrict__ bm1,
    const float* __restrict__ Wm2, const float* __restrict__ bm2)
{
    __shared__ float qs[16][CC];
    __shared__ float vns[16][CC];
    __shared__ float hs[16][CC];
    int tid = threadIdx.x, tx = tid & 31, wp = tid >> 5;
    int c0 = 4 * tx;
    int nb = blockIdx.x * 16;

    for (int idx = tid; idx < 16 * CC; idx += 256) {
        ((float*)qs)[idx]  = outq[(size_t)nb * CC + idx];
        ((float*)vns)[idx] = g_vn[(size_t)nb * CC + idx];
    }
    __syncthreads();

    {
        u64 acc[2][2];
        #pragma unroll
        for (int r = 0; r < 2; r++) { acc[r][0] = 0; acc[r][1] = 0; }
        for (int k = 0; k < CC; k += 2) {
            ulonglong2 wa = *(const ulonglong2*)(Wm1 + k * CC + c0);
            ulonglong2 wb = *(const ulonglong2*)(Wm1 + (k + 1) * CC + c0);
            #pragma unroll
            for (int r = 0; r < 2; r++) {
                float2 a = *(const float2*)(&qs[wp * 2 + r][k]);
                u64 p0 = pkb(a.x), p1 = pkb(a.y);
                fma2(acc[r][0], p0, wa.x);
                fma2(acc[r][1], p0, wa.y);
                fma2(acc[r][0], p1, wb.x);
                fma2(acc[r][1], p1, wb.y);
            }
        }
        for (int k = 0; k < CC; k += 2) {
            ulonglong2 wa = *(const ulonglong2*)(Wm1 + (CC + k) * CC + c0);
            ulonglong2 wb = *(const ulonglong2*)(Wm1 + (CC + k + 1) * CC + c0);
            #pragma unroll
            for (int r = 0; r < 2; r++) {
                float2 a = *(const float2*)(&vns[wp * 2 + r][k]);
                u64 p0 = pkb(a.x), p1 = pkb(a.y);
                fma2(acc[r][0], p0, wa.x);
                fma2(acc[r][1], p0, wa.y);
                fma2(acc[r][0], p1, wb.x);
                fma2(acc[r][1], p1, wb.y);
            }
        }
        float bv0 = bm1[c0], bv1 = bm1[c0 + 1], bv2 = bm1[c0 + 2], bv3 = bm1[c0 + 3];
        #pragma unroll
        for (int r = 0; r < 2; r++) {
            float a0, a1, a2, a3;
            up2(acc[r][0], a0, a1);
            up2(acc[r][1], a2, a3);
            hs[wp * 2 + r][c0]     = silu_f(a0 + bv0);
            hs[wp * 2 + r][c0 + 1] = silu_f(a1 + bv1);
            hs[wp * 2 + r][c0 + 2] = silu_f(a2 + bv2);
            hs[wp * 2 + r][c0 + 3] = silu_f(a3 + bv3);
        }
    }
    __syncwarp();

    u64 y0p[2][2];
    for (int ch = 0; ch < 3; ch++) {
        u64 acc[2][2];
        #pragma unroll
        for (int r = 0; r < 2; r++) { acc[r][0] = 0; acc[r][1] = 0; }
        for (int k = 0; k < CC; k += 2) {
            ulonglong2 wa = *(const ulonglong2*)(Wm2 + k * C3 + ch * CC + c0);
            ulonglong2 wb = *(const ulonglong2*)(Wm2 + (k + 1) * C3 + ch * CC + c0);
            #pragma unroll
            for (int r = 0; r < 2; r++) {
                float2 a = *(const float2*)(&hs[wp * 2 + r][k]);
                u64 p0 = pkb(a.x), p1 = pkb(a.y);
                fma2(acc[r][0], p0, wa.x);
                fma2(acc[r][1], p0, wa.y);
                fma2(acc[r][0], p1, wb.x);
                fma2(acc[r][1], p1, wb.y);
            }
        }
        if (ch == 0) {
            u64 bb0 = ld2(bm2 + c0), bb1 = ld2(bm2 + c0 + 2);
            #pragma unroll
            for (int r = 0; r < 2; r++) {
                y0p[r][0] = add2(acc[r][0], bb0);
                y0p[r][1] = add2(acc[r][1], bb1);
            }
        } else if (ch == 1) {
            u64 bb0 = ld2(bm2 + CC + c0), bb1 = ld2(bm2 + CC + c0 + 2);
            #pragma unroll
            for (int r = 0; r < 2; r++) {
                int node = nb + wp * 2 + r;
                u64 y1a = add2(acc[r][0], bb0);
                u64 y1b = add2(acc[r][1], bb1);
                #pragma unroll
                for (int v = 0; v < 3; v++) {
                    size_t off = ((size_t)node * 3 + v) * CC + c0;
                    u64 d0 = ld2(outmu + off);
                    u64 d1 = ld2(outmu + off + 2);
                    fma2(d0, y1a, ld2(g_mW + off));
                    fma2(d1, y1b, ld2(g_mW + off + 2));
                    st2(outmu + off, d0);
                    st2(outmu + off + 2, d1);
                }
            }
        } else {
            u64 bb0 = ld2(bm2 + 2 * CC + c0), bb1 = ld2(bm2 + 2 * CC + c0 + 2);
            #pragma unroll
            for (int r = 0; r < 2; r++) {
                int node = nb + wp * 2 + r;
                u64 y2a = add2(acc[r][0], bb0);
                u64 y2b = add2(acc[r][1], bb1);
                u64 d0 = add2(ld2(&qs[wp * 2 + r][c0]), y0p[r][0]);
                u64 d1 = add2(ld2(&qs[wp * 2 + r][c0 + 2]), y0p[r][1]);
                fma2(d0, y2a, ld2(g_sv + (size_t)node * CC + c0));
                fma2(d1, y2b, ld2(g_sv + (size_t)node * CC + c0 + 2));
                st2(outq + (size_t)node * CC + c0, d0);
                st2(outq + (size_t)node * CC + c0 + 2, d1);
            }
        }
    }
}

// ---------------- launch ----------------
extern "C" void kernel_launch(void* const* d_in, const int* in_sizes, int n_in,
                              void* d_out, int out_size)
{
    const float* q    = (const float*)d_in[0];
    const float* mu   = (const float*)d_in[1];
    const int*   eidx = (const int*)  d_in[2];
    const float* ew   = (const float*)d_in[3];
    const float* ev   = (const float*)d_in[4];
    const float* ea   = (const float*)d_in[5];
    const float* Wf   = (const float*)d_in[6];
    const float* bf   = (const float*)d_in[7];
    const float* W1   = (const float*)d_in[8];
    const float* b1   = (const float*)d_in[9];
    const float* W2   = (const float*)d_in[10];
    const float* b2   = (const float*)d_in[11];
    const float* Wmix = (const float*)d_in[12];
    const float* Wm1  = (const float*)d_in[13];
    const float* bm1  = (const float*)d_in[14];
    const float* Wm2  = (const float*)d_in[15];
    const float* bm2  = (const float*)d_in[16];

    float* outq  = (float*)d_out;
    float* outmu = outq + (size_t)NN * CC;

    // profiled slot = my launch index 3 => k_context (verify 116us reproduces)
    k_zero<<<(NN + 255) / 256, 256>>>();                                // 0
    k_bucket<<<(EE + 255) / 256, 256>>>(eidx);                          // 1
    k_dummy<<<(NN + 255) / 256, 256>>>();                               // 2 (tiny)
    k_context<<<(NN + 47) / 48, 256>>>(q, W1, b1, W2, b2);              // 3 <- profiled
    k_aggregate<<<NN, 192>>>(q, mu, eidx, ew, ev, ea, Wf, bf, outq, outmu); // 4
    k_mixA<<<NN / 16, 256>>>(outmu, Wmix);                              // 5
    k_mixB<<<NN / 16, 256>>>(outq, outmu, Wm1, bm1, Wm2, bm2);          // 6
}